// round 3
// baseline (speedup 1.0000x reference)
#include <cuda_runtime.h>

// PLE layers: 3 expert stacks (a, b, share), 8 experts each, dense softmax gating.
//   ea/eb/es[b,e,:] = x_σ[b,:] @ W_σ[e] + b_σ[e]      (B=16384, IN=256, D=128)
//   out_a = Σ wA[b,e]·ea + Σ wA[b,8+e]·es   (wA = softmax(x_a @ Ga^T), 16 gates)
//   out_b analogous; out_s over [ea,eb,es] with 24 gates.
// Fully fused single kernel: gates+softmax in smem, expert GEMMs via tf32
// mma.sync m16n8k8 folded directly into register output accumulators.

#define BT      16384
#define IN_D    256
#define EXP_D   128
#define NE      8
#define TB      64          // batch rows per CTA
#define KC      32          // K chunk for W streaming
#define XSS     260         // x smem stride (words): bank = 4*gid+tig, conflict-free
#define WSS     136         // w smem stride (words): bank = 8*tig+gid, conflict-free
#define GSS     57          // gate-weight smem stride (odd -> conflict-free row reads)
#define NTHREADS 256

__device__ __forceinline__ unsigned f2tf(float f) {
    unsigned u;
    asm("cvt.rna.tf32.f32 %0, %1;" : "=r"(u) : "f"(f));
    return u;
}

__device__ __forceinline__ void mma8(float& c0, float& c1, float& c2, float& c3,
                                     unsigned a0, unsigned a1, unsigned a2, unsigned a3,
                                     unsigned b0, unsigned b1) {
    asm volatile(
        "mma.sync.aligned.m16n8k8.row.col.f32.tf32.tf32.f32 "
        "{%0,%1,%2,%3}, {%4,%5,%6,%7}, {%8,%9}, {%0,%1,%2,%3};\n"
        : "+f"(c0), "+f"(c1), "+f"(c2), "+f"(c3)
        : "r"(a0), "r"(a1), "r"(a2), "r"(a3), "r"(b0), "r"(b1));
}

__global__ __launch_bounds__(NTHREADS, 1)
void ple_kernel(const float* __restrict__ xa, const float* __restrict__ xb,
                const float* __restrict__ xsh,
                const float* __restrict__ Wa, const float* __restrict__ ba,
                const float* __restrict__ Wb, const float* __restrict__ bb,
                const float* __restrict__ Wsx, const float* __restrict__ bsx,
                const float* __restrict__ Ga, const float* __restrict__ Gb,
                const float* __restrict__ Gq,
                float* __restrict__ out)
{
    extern __shared__ float smem[];
    float* xs  = smem;                 // TB*XSS : x tile (tf32 bits)
    float* ws  = xs + TB * XSS;        // KC*WSS : W chunk (tf32 bits)
    float* wsm = ws + KC * WSS;        // TB*GSS : gate weights [r][0:16 wA,16:32 wB,32:56 wS]
    float* bsm = wsm + TB * GSS;       // 3*1024 : biases [stack][e*128+d]

    const int tid  = threadIdx.x;
    const int lane = tid & 31;
    const int wid  = tid >> 5;
    const int gid  = lane >> 2;        // groupID (0..7)
    const int tig  = lane & 3;         // threadID-in-group (0..3)
    const int wm   = wid >> 2;         // warp row (0..1): 32 rows each
    const int wn   = wid & 3;          // warp col (0..3): 32 cols each
    const int row0 = blockIdx.x * TB;

    // biases -> smem
    for (int i = tid; i < 1024; i += NTHREADS) {
        bsm[i]        = ba[i];
        bsm[1024 + i] = bb[i];
        bsm[2048 + i] = bsx[i];
    }

    // ---------------- Phase 1: gate logits + softmax (full fp32) ----------------
    #pragma unroll
    for (int sg = 0; sg < 3; ++sg) {
        const float* X = (sg == 0) ? xa : (sg == 1) ? xb : xsh;
        const float* G = (sg == 0) ? Ga : (sg == 1) ? Gb : Gq;
        const int NG   = (sg == 2) ? 24 : 16;
        const int WOFF = sg * 16;      // 0 / 16 / 32

        __syncthreads();   // xs reuse + prev softmax writes
        const float4* src = (const float4*)(X + (size_t)row0 * IN_D);
        for (int idx = tid; idx < TB * IN_D / 4; idx += NTHREADS) {
            int r = idx >> 6, k4 = (idx & 63) << 2;
            float4 v = __ldg(src + idx);
            uint4 u;
            u.x = f2tf(v.x); u.y = f2tf(v.y); u.z = f2tf(v.z); u.w = f2tf(v.w);
            *(uint4*)(xs + r * XSS + k4) = u;
        }
        __syncthreads();

        for (int idx = tid; idx < TB * NG; idx += NTHREADS) {
            int r = idx / NG, g = idx - r * NG;
            const float4* xp = (const float4*)(xs + r * XSS);
            const float4* gp = (const float4*)(G + g * IN_D);
            float acc = 0.f;
            #pragma unroll 8
            for (int k = 0; k < IN_D / 4; ++k) {
                float4 xv = xp[k];
                float4 gv = __ldg(gp + k);
                acc += xv.x * gv.x; acc += xv.y * gv.y;
                acc += xv.z * gv.z; acc += xv.w * gv.w;
            }
            wsm[r * GSS + WOFF + g] = acc;
        }
        __syncthreads();

        if (tid < TB) {
            float* wr = wsm + tid * GSS + WOFF;
            float m = wr[0];
            for (int g = 1; g < NG; ++g) m = fmaxf(m, wr[g]);
            float s = 0.f;
            for (int g = 0; g < NG; ++g) { float e = expf(wr[g] - m); wr[g] = e; s += e; }
            float inv = 1.f / s;
            for (int g = 0; g < NG; ++g) wr[g] *= inv;
        }
    }

    // ---------------- Phase 2: expert GEMMs + gated fold ----------------
    float oa[2][4][4] = {}, ob[2][4][4] = {}, os[2][4][4] = {};

    #pragma unroll
    for (int sg = 0; sg < 3; ++sg) {
        const float* X = (sg == 0) ? xa : (sg == 1) ? xb : xsh;
        const float* W = (sg == 0) ? Wa : (sg == 1) ? Wb : Wsx;

        __syncthreads();   // all prior xs/wsm readers done
        const float4* src = (const float4*)(X + (size_t)row0 * IN_D);
        for (int idx = tid; idx < TB * IN_D / 4; idx += NTHREADS) {
            int r = idx >> 6, k4 = (idx & 63) << 2;
            float4 v = __ldg(src + idx);
            uint4 u;
            u.x = f2tf(v.x); u.y = f2tf(v.y); u.z = f2tf(v.z); u.w = f2tf(v.w);
            *(uint4*)(xs + r * XSS + k4) = u;
        }
        __syncthreads();

        for (int e = 0; e < NE; ++e) {
            float ec[2][4][4] = {};
            const float* We = W + e * IN_D * EXP_D;

            float4 rbuf[4];
            {
                const float4* s4 = (const float4*)We;
                #pragma unroll
                for (int j = 0; j < 4; ++j) rbuf[j] = __ldg(s4 + tid + j * NTHREADS);
            }

            for (int c = 0; c < IN_D / KC; ++c) {
                // stage chunk c (tf32-converted) into smem
                #pragma unroll
                for (int j = 0; j < 4; ++j) {
                    int idx = tid + j * NTHREADS;
                    int r = idx >> 5, c4 = (idx & 31) << 2;
                    uint4 u;
                    u.x = f2tf(rbuf[j].x); u.y = f2tf(rbuf[j].y);
                    u.z = f2tf(rbuf[j].z); u.w = f2tf(rbuf[j].w);
                    *(uint4*)(ws + r * WSS + c4) = u;
                }
                __syncthreads();

                // prefetch chunk c+1 (overlaps MMA below)
                if (c + 1 < IN_D / KC) {
                    const float4* s4 = (const float4*)(We + (c + 1) * KC * EXP_D);
                    #pragma unroll
                    for (int j = 0; j < 4; ++j) rbuf[j] = __ldg(s4 + tid + j * NTHREADS);
                }

                #pragma unroll
                for (int kk = 0; kk < KC / 8; ++kk) {
                    unsigned a0[2], a1[2], a2[2], a3[2];
                    #pragma unroll
                    for (int mt = 0; mt < 2; ++mt) {
                        const float* xr = xs + (wm * 32 + mt * 16 + gid) * XSS + c * KC + kk * 8;
                        a0[mt] = __float_as_uint(xr[tig]);
                        a1[mt] = __float_as_uint(xr[8 * XSS + tig]);
                        a2[mt] = __float_as_uint(xr[tig + 4]);
                        a3[mt] = __float_as_uint(xr[8 * XSS + tig + 4]);
                    }
                    #pragma unroll
                    for (int nt = 0; nt < 4; ++nt) {
                        int n = wn * 32 + nt * 8 + gid;
                        unsigned b0 = __float_as_uint(ws[(kk * 8 + tig) * WSS + n]);
                        unsigned b1 = __float_as_uint(ws[(kk * 8 + tig + 4) * WSS + n]);
                        #pragma unroll
                        for (int mt = 0; mt < 2; ++mt)
                            mma8(ec[mt][nt][0], ec[mt][nt][1], ec[mt][nt][2], ec[mt][nt][3],
                                 a0[mt], a1[mt], a2[mt], a3[mt], b0, b1);
                    }
                }
                __syncthreads();
            }

            // fold expert tile into gated output accumulators
            #pragma unroll
            for (int mt = 0; mt < 2; ++mt) {
                int rl = wm * 32 + mt * 16 + gid;
                float w1l = 0.f, w1h = 0.f, w2l = 0.f, w2h = 0.f, w3l = 0.f, w3h = 0.f;
                if (sg == 0) {
                    w1l = wsm[rl * GSS + e];        w1h = wsm[(rl + 8) * GSS + e];        // wA[e]  -> out_a
                    w2l = wsm[rl * GSS + 32 + e];   w2h = wsm[(rl + 8) * GSS + 32 + e];   // wS[e]  -> out_s
                } else if (sg == 1) {
                    w1l = wsm[rl * GSS + 16 + e];   w1h = wsm[(rl + 8) * GSS + 16 + e];   // wB[e]  -> out_b
                    w2l = wsm[rl * GSS + 40 + e];   w2h = wsm[(rl + 8) * GSS + 40 + e];   // wS[8+e]-> out_s
                } else {
                    w1l = wsm[rl * GSS + 8 + e];    w1h = wsm[(rl + 8) * GSS + 8 + e];    // wA[8+e]-> out_a
                    w2l = wsm[rl * GSS + 24 + e];   w2h = wsm[(rl + 8) * GSS + 24 + e];   // wB[8+e]-> out_b
                    w3l = wsm[rl * GSS + 48 + e];   w3h = wsm[(rl + 8) * GSS + 48 + e];   // wS[16+e]->out_s
                }
                #pragma unroll
                for (int nt = 0; nt < 4; ++nt) {
                    int c0 = wn * 32 + nt * 8 + 2 * tig;
                    const float* bp = bsm + sg * 1024 + e * EXP_D + c0;
                    float t0 = ec[mt][nt][0] + bp[0];
                    float t1 = ec[mt][nt][1] + bp[1];
                    float t2 = ec[mt][nt][2] + bp[0];
                    float t3 = ec[mt][nt][3] + bp[1];
                    if (sg == 0) {
                        oa[mt][nt][0] += w1l * t0; oa[mt][nt][1] += w1l * t1;
                        oa[mt][nt][2] += w1h * t2; oa[mt][nt][3] += w1h * t3;
                        os[mt][nt][0] += w2l * t0; os[mt][nt][1] += w2l * t1;
                        os[mt][nt][2] += w2h * t2; os[mt][nt][3] += w2h * t3;
                    } else if (sg == 1) {
                        ob[mt][nt][0] += w1l * t0; ob[mt][nt][1] += w1l * t1;
                        ob[mt][nt][2] += w1h * t2; ob[mt][nt][3] += w1h * t3;
                        os[mt][nt][0] += w2l * t0; os[mt][nt][1] += w2l * t1;
                        os[mt][nt][2] += w2h * t2; os[mt][nt][3] += w2h * t3;
                    } else {
                        oa[mt][nt][0] += w1l * t0; oa[mt][nt][1] += w1l * t1;
                        oa[mt][nt][2] += w1h * t2; oa[mt][nt][3] += w1h * t3;
                        ob[mt][nt][0] += w2l * t0; ob[mt][nt][1] += w2l * t1;
                        ob[mt][nt][2] += w2h * t2; ob[mt][nt][3] += w2h * t3;
                        os[mt][nt][0] += w3l * t0; os[mt][nt][1] += w3l * t1;
                        os[mt][nt][2] += w3h * t2; os[mt][nt][3] += w3h * t3;
                    }
                }
            }
        }
    }

    // ---------------- write out: [out_a | out_b | out_s], each [B,128] ----------------
    const size_t OS = (size_t)BT * EXP_D;
    #pragma unroll
    for (int mt = 0; mt < 2; ++mt) {
        int r = row0 + wm * 32 + mt * 16 + gid;
        #pragma unroll
        for (int nt = 0; nt < 4; ++nt) {
            int c0 = wn * 32 + nt * 8 + 2 * tig;
            size_t p0 = (size_t)r * EXP_D + c0;
            size_t p1 = (size_t)(r + 8) * EXP_D + c0;
            *(float2*)(out + p0)          = make_float2(oa[mt][nt][0], oa[mt][nt][1]);
            *(float2*)(out + p1)          = make_float2(oa[mt][nt][2], oa[mt][nt][3]);
            *(float2*)(out + OS + p0)     = make_float2(ob[mt][nt][0], ob[mt][nt][1]);
            *(float2*)(out + OS + p1)     = make_float2(ob[mt][nt][2], ob[mt][nt][3]);
            *(float2*)(out + 2 * OS + p0) = make_float2(os[mt][nt][0], os[mt][nt][1]);
            *(float2*)(out + 2 * OS + p1) = make_float2(os[mt][nt][2], os[mt][nt][3]);
        }
    }
}

extern "C" void kernel_launch(void* const* d_in, const int* in_sizes, int n_in,
                              void* d_out, int out_size) {
    (void)in_sizes; (void)n_in; (void)out_size;
    constexpr int SMEM_BYTES = (TB * XSS + KC * WSS + TB * GSS + 3 * 1024) * 4;  // ~110.8 KB
    cudaFuncSetAttribute(ple_kernel, cudaFuncAttributeMaxDynamicSharedMemorySize, SMEM_BYTES);
    ple_kernel<<<BT / TB, NTHREADS, SMEM_BYTES>>>(
        (const float*)d_in[0], (const float*)d_in[1], (const float*)d_in[2],
        (const float*)d_in[3], (const float*)d_in[4],
        (const float*)d_in[5], (const float*)d_in[6],
        (const float*)d_in[7], (const float*)d_in[8],
        (const float*)d_in[9], (const float*)d_in[10], (const float*)d_in[11],
        (float*)d_out);
}